// round 14
// baseline (speedup 1.0000x reference)
#include <cuda_runtime.h>
#include <cuda_bf16.h>
#include <cstdint>

// ---------------------------------------------------------------------------
// TransformerEncoderLayerWithROPE  (B=4, S=2048, D=1024, H=16, Dh=64, F=4096)
// fp32 SIMT f32x2 GEMMs for Q/K proj + logits + ctx (softmax-sensitive chain).
// mma.sync bf16 3-term-split GEMMs for V-proj, O-proj, FFN, with term-major
// MMA ordering to break same-accumulator RAW chains.
// ---------------------------------------------------------------------------

#define BB 4
#define SS 2048
#define DD 1024
#define HH 16
#define DH 64
#define FF 4096
#define MM (BB*SS)          // 8192

// ------------------------- scratch (device globals) ------------------------
__device__ float g_q  [MM*DD];
__device__ float g_k  [MM*DD];
__device__ float g_v  [MM*DD];
__device__ float g_ctx[MM*DD];
__device__ float g_att[MM*DD];
__device__ float g_h  [MM*DD];
__device__ float g_ff2[MM*DD];
__device__ float g_logits[268435456];   // 64 * 2048 * 2048

__device__ __nv_bfloat16 g_x0 [MM*DD];              // x 2-way split
__device__ __nv_bfloat16 g_x1 [MM*DD];
__device__ __nv_bfloat16 g_c0 [MM*DD];              // ctx 2-way split
__device__ __nv_bfloat16 g_c1 [MM*DD];
__device__ __nv_bfloat16 g_h_hi [MM*DD];
__device__ __nv_bfloat16 g_h_lo [MM*DD];
__device__ __nv_bfloat16 g_wvt_hi[(size_t)DD*DD], g_wvt_lo[(size_t)DD*DD];
__device__ __nv_bfloat16 g_wot_hi[(size_t)DD*DD], g_wot_lo[(size_t)DD*DD];
__device__ __nv_bfloat16 g_w1t_hi[(size_t)FF*DD],  g_w1t_lo[(size_t)FF*DD];
__device__ __nv_bfloat16 g_w2t_hi[(size_t)DD*FF],  g_w2t_lo[(size_t)DD*FF];
__device__ __nv_bfloat16 g_ff1_hi[(size_t)MM*FF],  g_ff1_lo[(size_t)MM*FF];

// ------------------------- packed fp32x2 helpers ---------------------------
__device__ __forceinline__ unsigned long long pack2(float x) {
    unsigned long long r;
    asm("mov.b64 %0, {%1, %1};" : "=l"(r) : "f"(x));
    return r;
}
__device__ __forceinline__ void ffma2(unsigned long long& d,
                                      unsigned long long a,
                                      unsigned long long b) {
    asm("fma.rn.f32x2 %0, %1, %2, %0;" : "+l"(d) : "l"(a), "l"(b));
}
__device__ __forceinline__ float2 unpack2(unsigned long long v) {
    float2 r;
    asm("mov.b64 {%0, %1}, %2;" : "=f"(r.x), "=f"(r.y) : "l"(v));
    return r;
}

// ------------------------------ fp32 GEMM ----------------------------------
#define TM 128
#define TKK 16

template<int TN_, int TRANSB>
__global__ __launch_bounds__(256, 2) void gemm_t(
    const float* __restrict__ A, int lda, long long sAb, long long sAh,
    const float* __restrict__ Bp, int ldb, long long sBb, long long sBh,
    float* __restrict__ C, int ldc, long long sCb, long long sCh,
    const float* __restrict__ bias,
    int K, float alpha, int relu)
{
    const int z  = blockIdx.z;
    const int zb = z >> 4;
    const int zh = z & 15;
    A  += zb * sAb + zh * sAh;
    Bp += zb * sBb + zh * sBh;
    C  += zb * sCb + zh * sCh;

    __shared__ __align__(16) float As[TKK][TM + 4];
    __shared__ __align__(16) float Bs[TKK][TN_ + 4];

    const int tid  = threadIdx.x;
    const int row0 = blockIdx.y * TM;
    const int col0 = blockIdx.x * TN_;

    const int ar = tid >> 1;
    const int ac = (tid & 1) * 8;
    const float* Aptr = A + (long long)(row0 + ar) * lda + ac;

    const float* Bptr;
    int br = 0, bc = 0;
    if (TRANSB) {
        br = tid >> 1; bc = (tid & 1) * 8;
        Bptr = Bp + (long long)(col0 + br) * ldb + bc;
    } else if (TN_ == 128) {
        Bptr = Bp + col0;
    } else {
        br = tid >> 4; bc = (tid & 15) * 4;
        Bptr = Bp + (long long)br * ldb + col0 + bc;
    }

    const int tx128 = tid & 15, ty128 = tid >> 4;
    const int tx64  = tid & 7,  ty64  = tid >> 3;

    constexpr int RPT = (TN_ == 128) ? 8 : 4;
    unsigned long long acc[RPT][4];
    #pragma unroll
    for (int i = 0; i < RPT; i++)
        #pragma unroll
        for (int j = 0; j < 4; j++) acc[i][j] = 0ull;

    float4 sa0, sa1, sb0, sb1;

    sa0 = *(const float4*)(Aptr + 0);
    sa1 = *(const float4*)(Aptr + 4);
    if (TRANSB) {
        sb0 = *(const float4*)(Bptr + 0);
        sb1 = *(const float4*)(Bptr + 4);
    } else if (TN_ == 128) {
        sb0 = *(const float4*)(Bptr + (long long)(tid >> 5)       * ldb + (tid & 31) * 4);
        sb1 = *(const float4*)(Bptr + (long long)((tid >> 5) + 8) * ldb + (tid & 31) * 4);
    } else {
        sb0 = *(const float4*)(Bptr);
    }

    const int ntiles = K / TKK;
    for (int t = 0; t < ntiles; t++) {
        As[ac + 0][ar] = sa0.x; As[ac + 1][ar] = sa0.y;
        As[ac + 2][ar] = sa0.z; As[ac + 3][ar] = sa0.w;
        As[ac + 4][ar] = sa1.x; As[ac + 5][ar] = sa1.y;
        As[ac + 6][ar] = sa1.z; As[ac + 7][ar] = sa1.w;
        if (TRANSB) {
            Bs[bc + 0][br] = sb0.x; Bs[bc + 1][br] = sb0.y;
            Bs[bc + 2][br] = sb0.z; Bs[bc + 3][br] = sb0.w;
            Bs[bc + 4][br] = sb1.x; Bs[bc + 5][br] = sb1.y;
            Bs[bc + 6][br] = sb1.z; Bs[bc + 7][br] = sb1.w;
        } else if (TN_ == 128) {
            *(float4*)&Bs[(tid >> 5)][(tid & 31) * 4]     = sb0;
            *(float4*)&Bs[(tid >> 5) + 8][(tid & 31) * 4] = sb1;
        } else {
            *(float4*)&Bs[br][bc] = sb0;
        }
        __syncthreads();

        if (t + 1 < ntiles) {
            const int k0 = (t + 1) * TKK;
            sa0 = *(const float4*)(Aptr + k0);
            sa1 = *(const float4*)(Aptr + k0 + 4);
            if (TRANSB) {
                sb0 = *(const float4*)(Bptr + k0);
                sb1 = *(const float4*)(Bptr + k0 + 4);
            } else if (TN_ == 128) {
                sb0 = *(const float4*)(Bptr + (long long)(k0 + (tid >> 5))     * ldb + (tid & 31) * 4);
                sb1 = *(const float4*)(Bptr + (long long)(k0 + (tid >> 5) + 8) * ldb + (tid & 31) * 4);
            } else {
                sb0 = *(const float4*)(Bptr + (long long)k0 * ldb);
            }
        }

        #pragma unroll
        for (int kk = 0; kk < TKK; kk++) {
            if (TN_ == 128) {
                float4 a0 = *(const float4*)&As[kk][ty128 * 4];
                float4 a1 = *(const float4*)&As[kk][64 + ty128 * 4];
                ulonglong2 b0 = *(const ulonglong2*)&Bs[kk][tx128 * 4];
                ulonglong2 b1 = *(const ulonglong2*)&Bs[kk][64 + tx128 * 4];
                float av[8] = {a0.x, a0.y, a0.z, a0.w, a1.x, a1.y, a1.z, a1.w};
                #pragma unroll
                for (int i = 0; i < RPT; i++) {
                    unsigned long long ap = pack2(av[i]);
                    ffma2(acc[i][0], ap, b0.x);
                    ffma2(acc[i][1], ap, b0.y);
                    ffma2(acc[i][2], ap, b1.x);
                    ffma2(acc[i][3], ap, b1.y);
                }
            } else {
                float4 a0 = *(const float4*)&As[kk][ty64 * 4];
                ulonglong2 b0 = *(const ulonglong2*)&Bs[kk][tx64 * 8];
                ulonglong2 b1 = *(const ulonglong2*)&Bs[kk][tx64 * 8 + 4];
                float av[4] = {a0.x, a0.y, a0.z, a0.w};
                #pragma unroll
                for (int i = 0; i < RPT; i++) {
                    unsigned long long ap = pack2(av[i]);
                    ffma2(acc[i][0], ap, b0.x);
                    ffma2(acc[i][1], ap, b0.y);
                    ffma2(acc[i][2], ap, b1.x);
                    ffma2(acc[i][3], ap, b1.y);
                }
            }
        }
        __syncthreads();
    }

    #pragma unroll
    for (int i = 0; i < RPT; i++) {
        int mm, nb;
        if (TN_ == 128) { mm = ty128 * 4 + (i & 3) + ((i >> 2) << 6); nb = tx128 * 4; }
        else            { mm = ty64 * 4 + i;                          nb = tx64 * 8;  }
        const long long base = (long long)(row0 + mm) * ldc + col0;
        #pragma unroll
        for (int j = 0; j < 4; j++) {
            float2 p = unpack2(acc[i][j]);
            int gn;
            if (TN_ == 128) gn = (j < 2) ? (nb + j * 2) : (64 + nb + (j - 2) * 2);
            else            gn = nb + j * 2;
            float v0 = alpha * p.x;
            float v1 = alpha * p.y;
            if (bias) { v0 += bias[col0 + gn]; v1 += bias[col0 + gn + 1]; }
            if (relu) { v0 = fmaxf(v0, 0.f); v1 = fmaxf(v1, 0.f); }
            *(float2*)&C[base + gn] = make_float2(v0, v1);
        }
    }
}

// ---------------------- mma.sync bf16 3-term-split GEMM --------------------
// D[128x128 tile] ~= a0b0 + a0b1 + a1b0  (err ~2^-17; linear-path only!)
// Term-major MMA ordering: all 16 independent accs per term pass, so the
// same-acc reuse distance is 16 MMAs (covers HMMA RAW latency).
#define MPAD 24      // smem row stride in bf16 (48 B)
#define TILEB 6144   // one 128 x 16 tile: 128*MPAD*2 bytes
#define TILEU4 384   // TILEB / 16

__device__ __forceinline__ void ldsm4(uint32_t* r, uint32_t a) {
    asm volatile("ldmatrix.sync.aligned.m8n8.x4.shared.b16 {%0,%1,%2,%3}, [%4];"
        : "=r"(r[0]), "=r"(r[1]), "=r"(r[2]), "=r"(r[3]) : "r"(a));
}
__device__ __forceinline__ void ldsm2(uint32_t* r, uint32_t a) {
    asm volatile("ldmatrix.sync.aligned.m8n8.x2.shared.b16 {%0,%1}, [%2];"
        : "=r"(r[0]), "=r"(r[1]) : "r"(a));
}
__device__ __forceinline__ void mma16816(float* c, const uint32_t* a, const uint32_t* b) {
    asm volatile("mma.sync.aligned.m16n8k16.row.col.f32.bf16.bf16.f32 "
        "{%0,%1,%2,%3},{%4,%5,%6,%7},{%8,%9},{%0,%1,%2,%3};"
        : "+f"(c[0]), "+f"(c[1]), "+f"(c[2]), "+f"(c[3])
        : "r"(a[0]), "r"(a[1]), "r"(a[2]), "r"(a[3]), "r"(b[0]), "r"(b[1]));
}

template<int MODE>
__global__ __launch_bounds__(256, 2) void gemm_mma_t(
    const __nv_bfloat16* __restrict__ A0, const __nv_bfloat16* __restrict__ A1,
    const __nv_bfloat16* __restrict__ B0, const __nv_bfloat16* __restrict__ B1,
    const float* __restrict__ bias,
    float* __restrict__ Cf,
    __nv_bfloat16* __restrict__ Chi, __nv_bfloat16* __restrict__ Clo,
    int K, int N)      // MODE 0: fp32 C + bias; MODE 1: bias + relu + split bf16
{
    constexpr int NBUF = 4;
    extern __shared__ char dyns[];

    const int tid  = threadIdx.x;
    const int lane = tid & 31;
    const int wid  = tid >> 5;
    const int warp_m = wid >> 2;
    const int warp_n = wid & 3;
    const int row0 = blockIdx.y * 128;
    const int col0 = blockIdx.x * 128;
    const int ldu  = K >> 3;

    const int lrow = tid >> 1;
    const int lcol = tid & 1;
    const size_t aidx = (size_t)(row0 + lrow) * ldu + lcol;
    const size_t bidx = (size_t)(col0 + lrow) * ldu + lcol;
    const int sidx = lrow * 3 + lcol;

    const uint32_t su = (uint32_t)__cvta_generic_to_shared(dyns);

    float acc[4][4][4];
    #pragma unroll
    for (int m = 0; m < 4; m++)
        #pragma unroll
        for (int n = 0; n < 4; n++)
            #pragma unroll
            for (int j = 0; j < 4; j++) acc[m][n][j] = 0.f;

    const uint32_t a_off = ((uint32_t)(warp_m * 64 + (lane & 15)) * MPAD +
                            (uint32_t)(lane >> 4) * 8) * 2;
    const uint32_t b_off = ((uint32_t)(warp_n * 32 + (lane & 7)) * MPAD +
                            (uint32_t)((lane >> 3) & 1) * 8) * 2;

    uint4 sA0, sA1, sB0, sB1;
    sA0 = ((const uint4*)A0)[aidx];
    sA1 = ((const uint4*)A1)[aidx];
    sB0 = ((const uint4*)B0)[bidx];
    sB1 = ((const uint4*)B1)[bidx];
    {
        uint4* t = (uint4*)dyns;
        t[0 * TILEU4 + sidx] = sA0;
        t[1 * TILEU4 + sidx] = sA1;
        t[2 * TILEU4 + sidx] = sB0;
        t[3 * TILEU4 + sidx] = sB1;
    }
    __syncthreads();

    const int NC = K >> 4;
    for (int c = 0; c < NC; c++) {
        const int cur = c & 1;
        if (c + 1 < NC) {
            const size_t a2i = aidx + (size_t)(c + 1) * 2;
            const size_t b2i = bidx + (size_t)(c + 1) * 2;
            sA0 = ((const uint4*)A0)[a2i];
            sA1 = ((const uint4*)A1)[a2i];
            sB0 = ((const uint4*)B0)[b2i];
            sB1 = ((const uint4*)B1)[b2i];
        }

        const uint32_t tb = su + (uint32_t)(cur * NBUF) * TILEB;
        uint32_t bf0[4][2], bf1[4][2];
        #pragma unroll
        for (int nt = 0; nt < 4; nt++) {
            const uint32_t o = b_off + (uint32_t)(nt * 8 * MPAD * 2);
            ldsm2(bf0[nt], tb + 2 * TILEB + o);
            ldsm2(bf1[nt], tb + 3 * TILEB + o);
        }

        uint32_t ar[4][4];
        // ---- term pass 1: a0 * b0  (16 independent accumulators)
        #pragma unroll
        for (int mt = 0; mt < 4; mt++)
            ldsm4(ar[mt], tb + a_off + (uint32_t)(mt * 16 * MPAD * 2));
        #pragma unroll
        for (int mt = 0; mt < 4; mt++)
            #pragma unroll
            for (int nt = 0; nt < 4; nt++)
                mma16816(acc[mt][nt], ar[mt], bf0[nt]);
        // ---- term pass 2: a0 * b1  (same accs revisited 16 MMAs later)
        #pragma unroll
        for (int mt = 0; mt < 4; mt++)
            #pragma unroll
            for (int nt = 0; nt < 4; nt++)
                mma16816(acc[mt][nt], ar[mt], bf1[nt]);
        // ---- term pass 3: a1 * b0  (reload A-lo into the same regs)
        #pragma unroll
        for (int mt = 0; mt < 4; mt++)
            ldsm4(ar[mt], tb + TILEB + a_off + (uint32_t)(mt * 16 * MPAD * 2));
        #pragma unroll
        for (int mt = 0; mt < 4; mt++)
            #pragma unroll
            for (int nt = 0; nt < 4; nt++)
                mma16816(acc[mt][nt], ar[mt], bf0[nt]);

        if (c + 1 < NC) {
            uint4* t = (uint4*)(dyns + (size_t)((cur ^ 1) * NBUF) * TILEB);
            t[0 * TILEU4 + sidx] = sA0;
            t[1 * TILEU4 + sidx] = sA1;
            t[2 * TILEU4 + sidx] = sB0;
            t[3 * TILEU4 + sidx] = sB1;
        }
        __syncthreads();
    }

    // ---- epilogue
    #pragma unroll
    for (int mt = 0; mt < 4; mt++) {
        #pragma unroll
        for (int nt = 0; nt < 4; nt++) {
            const int r0 = row0 + warp_m * 64 + mt * 16 + (lane >> 2);
            const int cb = col0 + warp_n * 32 + nt * 8 + (lane & 3) * 2;
            const float* cc = acc[mt][nt];
            #pragma unroll
            for (int half = 0; half < 2; half++) {
                const int r = r0 + half * 8;
                float v0 = cc[half * 2 + 0] + bias[cb];
                float v1 = cc[half * 2 + 1] + bias[cb + 1];
                if (MODE == 0) {
                    *(float2*)&Cf[(size_t)r * N + cb] = make_float2(v0, v1);
                } else {
                    v0 = fmaxf(v0, 0.f); v1 = fmaxf(v1, 0.f);
                    __nv_bfloat16 h0 = __float2bfloat16(v0);
                    __nv_bfloat16 h1 = __float2bfloat16(v1);
                    __nv_bfloat162 hv; hv.x = h0; hv.y = h1;
                    __nv_bfloat162 lv;
                    lv.x = __float2bfloat16(v0 - __bfloat162float(h0));
                    lv.y = __float2bfloat16(v1 - __bfloat162float(h1));
                    *(__nv_bfloat162*)&Chi[(size_t)r * N + cb] = hv;
                    *(__nv_bfloat162*)&Clo[(size_t)r * N + cb] = lv;
                }
            }
        }
    }
}

// ------------------- weight transpose + bf16 hi/lo split -------------------
// in: [K][N] fp32  ->  hiT/loT: [N][K] bf16
__global__ void tsplit_kernel(const float* __restrict__ in,
                              __nv_bfloat16* __restrict__ hiT,
                              __nv_bfloat16* __restrict__ loT,
                              int K, int N)
{
    __shared__ float t[32][33];
    const int n0 = blockIdx.x * 32;
    const int k0 = blockIdx.y * 32;
    const int tx = threadIdx.x, ty = threadIdx.y;   // 32 x 8
    #pragma unroll
    for (int i = 0; i < 32; i += 8)
        t[ty + i][tx] = in[(size_t)(k0 + ty + i) * N + n0 + tx];
    __syncthreads();
    #pragma unroll
    for (int i = 0; i < 32; i += 8) {
        float v = t[tx][ty + i];
        __nv_bfloat16 h = __float2bfloat16(v);
        size_t o = (size_t)(n0 + ty + i) * K + k0 + tx;
        hiT[o] = h;
        loT[o] = __float2bfloat16(v - __bfloat162float(h));
    }
}

// ------------------ elementwise 2-way fp32->bf16 split ---------------------
__global__ __launch_bounds__(256) void split2_kernel(
    const float* __restrict__ in,
    __nv_bfloat16* __restrict__ o0, __nv_bfloat16* __restrict__ o1)
{
    const int i0 = (blockIdx.x * 256 + threadIdx.x) * 4;
    float4 v = *(const float4*)(in + i0);
    const float* vv = &v.x;
    __nv_bfloat162 h2[2], l2[2];
    #pragma unroll
    for (int j = 0; j < 4; j++) {
        float x = vv[j];
        __nv_bfloat16 h = __float2bfloat16(x);
        ((__nv_bfloat16*)h2)[j] = h;
        ((__nv_bfloat16*)l2)[j] = __float2bfloat16(x - __bfloat162float(h));
    }
    *(uint2*)(o0 + i0) = *(uint2*)h2;
    *(uint2*)(o1 + i0) = *(uint2*)l2;
}

// ------------------------------ RoPE ---------------------------------------
__global__ void rope_kernel(float* __restrict__ q, float* __restrict__ k)
{
    int warp = blockIdx.x * 8 + (threadIdx.x >> 5);
    int lane = threadIdx.x & 31;
    const int NROWS = BB * SS * HH;
    if (warp >= 2 * NROWS) return;
    float* p;
    int r = warp;
    if (r < NROWS) p = q + (long long)r * DH;
    else { r -= NROWS; p = k + (long long)r * DH; }
    int s = (r / HH) & (SS - 1);

    float t0 = p[2 * lane];
    float t1 = p[2 * lane + 1];
    int m0 = (2 * lane) & 31;
    int m1 = (2 * lane + 1) & 31;
    const float c = 0.41524101186092026f;     // log2(10000)/32
    float fs = (float)s;
    float a  = fs * exp2f(-(float)m0 * c);
    float b  = fs * exp2f(-(float)m1 * c);
    __syncwarp();
    p[lane]      = t0 * a - t1 * b;
    p[32 + lane] = t0 * b + t1 * a;
}

// ------------------------------ softmax ------------------------------------
__global__ __launch_bounds__(256) void softmax_kernel(float* __restrict__ logits)
{
    long long row = blockIdx.x;
    float* p = logits + row * 2048;
    int tid = threadIdx.x;
    __shared__ float red[256];

    float v[8];
    float mx = -3.402823466e38f;
    #pragma unroll
    for (int i = 0; i < 8; i++) { v[i] = p[tid + i * 256]; mx = fmaxf(mx, v[i]); }
    red[tid] = mx; __syncthreads();
    for (int st = 128; st > 0; st >>= 1) {
        if (tid < st) red[tid] = fmaxf(red[tid], red[tid + st]);
        __syncthreads();
    }
    mx = red[0]; __syncthreads();

    float s = 0.f;
    #pragma unroll
    for (int i = 0; i < 8; i++) { v[i] = expf(v[i] - mx); s += v[i]; }
    red[tid] = s; __syncthreads();
    for (int st = 128; st > 0; st >>= 1) {
        if (tid < st) red[tid] += red[tid + st];
        __syncthreads();
    }
    float inv = 1.f / red[0];
    #pragma unroll
    for (int i = 0; i < 8; i++) p[tid + i * 256] = v[i] * inv;
}

// --------------------------- residual + layernorm --------------------------
__global__ __launch_bounds__(256) void add_ln_kernel(
    const float* __restrict__ a, const float* __restrict__ b,
    const float* __restrict__ g, const float* __restrict__ be,
    float* __restrict__ out,
    __nv_bfloat16* __restrict__ ohi, __nv_bfloat16* __restrict__ olo)
{
    __shared__ float red[256];
    long long row = blockIdx.x;
    int tid = threadIdx.x;
    const float* pa = a + row * DD;
    const float* pb = b + row * DD;

    float v[4]; float s = 0.f;
    #pragma unroll
    for (int i = 0; i < 4; i++) { int c = tid + i * 256; v[i] = pa[c] + pb[c]; s += v[i]; }
    red[tid] = s; __syncthreads();
    for (int st = 128; st > 0; st >>= 1) { if (tid < st) red[tid] += red[tid + st]; __syncthreads(); }
    float mean = red[0] * (1.f / 1024.f);
    __syncthreads();

    float s2 = 0.f;
    #pragma unroll
    for (int i = 0; i < 4; i++) { float d = v[i] - mean; s2 += d * d; }
    red[tid] = s2; __syncthreads();
    for (int st = 128; st > 0; st >>= 1) { if (tid < st) red[tid] += red[tid + st]; __syncthreads(); }
    float var = red[0] * (1.f / 1024.f);
    float rs = 1.f / sqrtf(var + 1e-5f);

    float* po = out + row * DD;
    #pragma unroll
    for (int i = 0; i < 4; i++) {
        int c = tid + i * 256;
        float val = (v[i] - mean) * rs * g[c] + be[c];
        po[c] = val;
        if (ohi) {
            __nv_bfloat16 h = __float2bfloat16(val);
            ohi[row * DD + c] = h;
            olo[row * DD + c] = __float2bfloat16(val - __bfloat162float(h));
        }
    }
}

// ------------------------------- launcher ----------------------------------
extern "C" void kernel_launch(void* const* d_in, const int* in_sizes, int n_in,
                              void* d_out, int out_size)
{
    (void)in_sizes; (void)n_in; (void)out_size;
    const float* x   = (const float*)d_in[0];
    const float* wq  = (const float*)d_in[1];
    const float* bq  = (const float*)d_in[2];
    const float* wk  = (const float*)d_in[3];
    const float* bk  = (const float*)d_in[4];
    const float* wv  = (const float*)d_in[5];
    const float* bv  = (const float*)d_in[6];
    const float* wo  = (const float*)d_in[7];
    const float* bo  = (const float*)d_in[8];
    const float* w1  = (const float*)d_in[9];
    const float* b1  = (const float*)d_in[10];
    const float* w2  = (const float*)d_in[11];
    const float* b2  = (const float*)d_in[12];
    const float* g1  = (const float*)d_in[13];
    const float* be1 = (const float*)d_in[14];
    const float* g2  = (const float*)d_in[15];
    const float* be2 = (const float*)d_in[16];
    float* out = (float*)d_out;

    float *q, *k, *v, *ctx, *att, *h, *ff2, *lg;
    __nv_bfloat16 *x0, *x1, *c0, *c1, *hhi, *hlo;
    __nv_bfloat16 *wvh, *wvl, *woh, *wol;
    __nv_bfloat16 *w1h, *w1l, *w2h, *w2l, *f1h, *f1l;
    cudaGetSymbolAddress((void**)&q,    g_q);
    cudaGetSymbolAddress((void**)&k,    g_k);
    cudaGetSymbolAddress((void**)&v,    g_v);
    cudaGetSymbolAddress((void**)&ctx,  g_ctx);
    cudaGetSymbolAddress((void**)&att,  g_att);
    cudaGetSymbolAddress((void**)&h,    g_h);
    cudaGetSymbolAddress((void**)&ff2,  g_ff2);
    cudaGetSymbolAddress((void**)&lg,   g_logits);
    cudaGetSymbolAddress((void**)&x0,   g_x0);
    cudaGetSymbolAddress((void**)&x1,   g_x1);
    cudaGetSymbolAddress((void**)&c0,   g_c0);
    cudaGetSymbolAddress((void**)&c1,   g_c1);
    cudaGetSymbolAddress((void**)&hhi,  g_h_hi);
    cudaGetSymbolAddress((void**)&hlo,  g_h_lo);
    cudaGetSymbolAddress((void**)&wvh,  g_wvt_hi); cudaGetSymbolAddress((void**)&wvl, g_wvt_lo);
    cudaGetSymbolAddress((void**)&woh,  g_wot_hi); cudaGetSymbolAddress((void**)&wol, g_wot_lo);
    cudaGetSymbolAddress((void**)&w1h,  g_w1t_hi); cudaGetSymbolAddress((void**)&w1l, g_w1t_lo);
    cudaGetSymbolAddress((void**)&w2h,  g_w2t_hi); cudaGetSymbolAddress((void**)&w2l, g_w2t_lo);
    cudaGetSymbolAddress((void**)&f1h,  g_ff1_hi); cudaGetSymbolAddress((void**)&f1l, g_ff1_lo);

    const int SM3 = 2 * 4 * TILEB;   // 49152 (double-buffered, 4 tiles/stage)
    cudaFuncSetAttribute(gemm_mma_t<0>, cudaFuncAttributeMaxDynamicSharedMemorySize, SM3);
    cudaFuncSetAttribute(gemm_mma_t<1>, cudaFuncAttributeMaxDynamicSharedMemorySize, SM3);

    dim3 blk(256);
    const long long sQ  = (long long)SS * DD;
    const long long sLb = (long long)HH * SS * SS;
    const long long sLh = (long long)SS * SS;

    dim3 gP(DD / 128, MM / TM, 1);

    // prep: x split (for V proj) + weight transpose/splits for mma path
    split2_kernel<<<MM * DD / 1024, 256>>>(x, x0, x1);
    tsplit_kernel<<<dim3(DD / 32, DD / 32), dim3(32, 8)>>>(wv, wvh, wvl, DD, DD);
    tsplit_kernel<<<dim3(DD / 32, DD / 32), dim3(32, 8)>>>(wo, woh, wol, DD, DD);
    tsplit_kernel<<<dim3(FF / 32, DD / 32), dim3(32, 8)>>>(w1, w1h, w1l, DD, FF);
    tsplit_kernel<<<dim3(DD / 32, FF / 32), dim3(32, 8)>>>(w2, w2h, w2l, FF, DD);

    // Q/K projections: fp32 (RoPE amplifies q/k error ~1e6x into the logits)
    gemm_t<128,0><<<gP, blk>>>(x, DD, 0, 0, wq, DD, 0, 0, q, DD, 0, 0, bq, DD, 1.f, 0);
    gemm_t<128,0><<<gP, blk>>>(x, DD, 0, 0, wk, DD, 0, 0, k, DD, 0, 0, bk, DD, 1.f, 0);

    // V projection: 3-term mma (linear path, err ~2^-17 OK)
    gemm_mma_t<0><<<dim3(DD/128, MM/128), blk, SM3>>>(
        x0, x1, wvh, wvl, bv, v, nullptr, nullptr, DD, DD);

    rope_kernel<<<(2 * BB * SS * HH) / 8, 256>>>(q, k);

    // logits = (Q @ K^T) / 8  (fp32 — softmax-sensitive)
    gemm_t<128,1><<<dim3(SS / 128, SS / TM, BB * HH), blk>>>(
        q, DD, sQ, DH,  k, DD, sQ, DH,  lg, SS, sLb, sLh,
        nullptr, DH, 0.125f, 0);

    softmax_kernel<<<BB * HH * SS, 256>>>(lg);

    // ctx = attn @ V (fp32)
    gemm_t<64,0><<<dim3(1, SS / TM, BB * HH), blk>>>(
        lg, SS, sLb, sLh,  v, DD, sQ, DH,  ctx, DD, sQ, DH,
        nullptr, SS, 1.f, 0);

    // ctx split + output projection (3-term mma)
    split2_kernel<<<MM * DD / 1024, 256>>>(ctx, c0, c1);
    gemm_mma_t<0><<<dim3(DD/128, MM/128), blk, SM3>>>(
        c0, c1, woh, wol, bo, att, nullptr, nullptr, DD, DD);

    // h = LN(x + att), also emit bf16 split of h
    add_ln_kernel<<<MM, 256>>>(x, att, g1, be1, h, hhi, hlo);

    // FFN (3-term mma)
    gemm_mma_t<1><<<dim3(FF/128, MM/128), blk, SM3>>>(
        hhi, hlo, w1h, w1l, b1, nullptr, f1h, f1l, DD, FF);
    gemm_mma_t<0><<<dim3(DD/128, MM/128), blk, SM3>>>(
        f1h, f1l, w2h, w2l, b2, ff2, nullptr, nullptr, FF, DD);

    // out = LN(h + ff)
    add_ln_kernel<<<MM, 256>>>(h, ff2, g2, be2, out, nullptr, nullptr);
}

// round 15
// speedup vs baseline: 1.1631x; 1.1631x over previous
#include <cuda_runtime.h>
#include <cuda_bf16.h>
#include <cstdint>

// ---------------------------------------------------------------------------
// TransformerEncoderLayerWithROPE  (B=4, S=2048, D=1024, H=16, Dh=64, F=4096)
// fp32 SIMT f32x2 GEMMs for Q/K proj + ctx (softmax-sensitive chain).
// logits on HMMA via 6-term 3-way-bf16 split (residual ~2^-23, fp32-class).
// mma.sync bf16 3-term-split GEMMs for V-proj, O-proj, FFN (R11-proven form).
// ---------------------------------------------------------------------------

#define BB 4
#define SS 2048
#define DD 1024
#define HH 16
#define DH 64
#define FF 4096
#define MM (BB*SS)          // 8192

// ------------------------- scratch (device globals) ------------------------
__device__ float g_q  [MM*DD];
__device__ float g_k  [MM*DD];
__device__ float g_v  [MM*DD];
__device__ float g_ctx[MM*DD];
__device__ float g_att[MM*DD];
__device__ float g_h  [MM*DD];
__device__ float g_ff2[MM*DD];
__device__ float g_logits[268435456];   // 64 * 2048 * 2048

__device__ __nv_bfloat16 g_x0 [MM*DD];              // x 2-way split
__device__ __nv_bfloat16 g_x1 [MM*DD];
__device__ __nv_bfloat16 g_c0 [MM*DD];              // ctx 2-way split
__device__ __nv_bfloat16 g_c1 [MM*DD];
__device__ __nv_bfloat16 g_h_hi [MM*DD];
__device__ __nv_bfloat16 g_h_lo [MM*DD];
__device__ __nv_bfloat16 g_q0[MM*DD], g_q1[MM*DD], g_q2[MM*DD];  // q_rot 3-way
__device__ __nv_bfloat16 g_k0[MM*DD], g_k1[MM*DD], g_k2[MM*DD];  // k_rot 3-way
__device__ __nv_bfloat16 g_wvt_hi[(size_t)DD*DD], g_wvt_lo[(size_t)DD*DD];
__device__ __nv_bfloat16 g_wot_hi[(size_t)DD*DD], g_wot_lo[(size_t)DD*DD];
__device__ __nv_bfloat16 g_w1t_hi[(size_t)FF*DD],  g_w1t_lo[(size_t)FF*DD];
__device__ __nv_bfloat16 g_w2t_hi[(size_t)DD*FF],  g_w2t_lo[(size_t)DD*FF];
__device__ __nv_bfloat16 g_ff1_hi[(size_t)MM*FF],  g_ff1_lo[(size_t)MM*FF];

// ------------------------- packed fp32x2 helpers ---------------------------
__device__ __forceinline__ unsigned long long pack2(float x) {
    unsigned long long r;
    asm("mov.b64 %0, {%1, %1};" : "=l"(r) : "f"(x));
    return r;
}
__device__ __forceinline__ void ffma2(unsigned long long& d,
                                      unsigned long long a,
                                      unsigned long long b) {
    asm("fma.rn.f32x2 %0, %1, %2, %0;" : "+l"(d) : "l"(a), "l"(b));
}
__device__ __forceinline__ float2 unpack2(unsigned long long v) {
    float2 r;
    asm("mov.b64 {%0, %1}, %2;" : "=f"(r.x), "=f"(r.y) : "l"(v));
    return r;
}

// ------------------------------ fp32 GEMM ----------------------------------
#define TM 128
#define TKK 16

template<int TN_, int TRANSB>
__global__ __launch_bounds__(256, 2) void gemm_t(
    const float* __restrict__ A, int lda, long long sAb, long long sAh,
    const float* __restrict__ Bp, int ldb, long long sBb, long long sBh,
    float* __restrict__ C, int ldc, long long sCb, long long sCh,
    const float* __restrict__ bias,
    int K, float alpha, int relu)
{
    const int z  = blockIdx.z;
    const int zb = z >> 4;
    const int zh = z & 15;
    A  += zb * sAb + zh * sAh;
    Bp += zb * sBb + zh * sBh;
    C  += zb * sCb + zh * sCh;

    __shared__ __align__(16) float As[TKK][TM + 4];
    __shared__ __align__(16) float Bs[TKK][TN_ + 4];

    const int tid  = threadIdx.x;
    const int row0 = blockIdx.y * TM;
    const int col0 = blockIdx.x * TN_;

    const int ar = tid >> 1;
    const int ac = (tid & 1) * 8;
    const float* Aptr = A + (long long)(row0 + ar) * lda + ac;

    const float* Bptr;
    int br = 0, bc = 0;
    if (TRANSB) {
        br = tid >> 1; bc = (tid & 1) * 8;
        Bptr = Bp + (long long)(col0 + br) * ldb + bc;
    } else if (TN_ == 128) {
        Bptr = Bp + col0;
    } else {
        br = tid >> 4; bc = (tid & 15) * 4;
        Bptr = Bp + (long long)br * ldb + col0 + bc;
    }

    const int tx128 = tid & 15, ty128 = tid >> 4;
    const int tx64  = tid & 7,  ty64  = tid >> 3;

    constexpr int RPT = (TN_ == 128) ? 8 : 4;
    unsigned long long acc[RPT][4];
    #pragma unroll
    for (int i = 0; i < RPT; i++)
        #pragma unroll
        for (int j = 0; j < 4; j++) acc[i][j] = 0ull;

    float4 sa0, sa1, sb0, sb1;

    sa0 = *(const float4*)(Aptr + 0);
    sa1 = *(const float4*)(Aptr + 4);
    if (TRANSB) {
        sb0 = *(const float4*)(Bptr + 0);
        sb1 = *(const float4*)(Bptr + 4);
    } else if (TN_ == 128) {
        sb0 = *(const float4*)(Bptr + (long long)(tid >> 5)       * ldb + (tid & 31) * 4);
        sb1 = *(const float4*)(Bptr + (long long)((tid >> 5) + 8) * ldb + (tid & 31) * 4);
    } else {
        sb0 = *(const float4*)(Bptr);
    }

    const int ntiles = K / TKK;
    for (int t = 0; t < ntiles; t++) {
        As[ac + 0][ar] = sa0.x; As[ac + 1][ar] = sa0.y;
        As[ac + 2][ar] = sa0.z; As[ac + 3][ar] = sa0.w;
        As[ac + 4][ar] = sa1.x; As[ac + 5][ar] = sa1.y;
        As[ac + 6][ar] = sa1.z; As[ac + 7][ar] = sa1.w;
        if (TRANSB) {
            Bs[bc + 0][br] = sb0.x; Bs[bc + 1][br] = sb0.y;
            Bs[bc + 2][br] = sb0.z; Bs[bc + 3][br] = sb0.w;
            Bs[bc + 4][br] = sb1.x; Bs[bc + 5][br] = sb1.y;
            Bs[bc + 6][br] = sb1.z; Bs[bc + 7][br] = sb1.w;
        } else if (TN_ == 128) {
            *(float4*)&Bs[(tid >> 5)][(tid & 31) * 4]     = sb0;
            *(float4*)&Bs[(tid >> 5) + 8][(tid & 31) * 4] = sb1;
        } else {
            *(float4*)&Bs[br][bc] = sb0;
        }
        __syncthreads();

        if (t + 1 < ntiles) {
            const int k0 = (t + 1) * TKK;
            sa0 = *(const float4*)(Aptr + k0);
            sa1 = *(const float4*)(Aptr + k0 + 4);
            if (TRANSB) {
                sb0 = *(const float4*)(Bptr + k0);
                sb1 = *(const float4*)(Bptr + k0 + 4);
            } else if (TN_ == 128) {
                sb0 = *(const float4*)(Bptr + (long long)(k0 + (tid >> 5))     * ldb + (tid & 31) * 4);
                sb1 = *(const float4*)(Bptr + (long long)(k0 + (tid >> 5) + 8) * ldb + (tid & 31) * 4);
            } else {
                sb0 = *(const float4*)(Bptr + (long long)k0 * ldb);
            }
        }

        #pragma unroll
        for (int kk = 0; kk < TKK; kk++) {
            if (TN_ == 128) {
                float4 a0 = *(const float4*)&As[kk][ty128 * 4];
                float4 a1 = *(const float4*)&As[kk][64 + ty128 * 4];
                ulonglong2 b0 = *(const ulonglong2*)&Bs[kk][tx128 * 4];
                ulonglong2 b1 = *(const ulonglong2*)&Bs[kk][64 + tx128 * 4];
                float av[8] = {a0.x, a0.y, a0.z, a0.w, a1.x, a1.y, a1.z, a1.w};
                #pragma unroll
                for (int i = 0; i < RPT; i++) {
                    unsigned long long ap = pack2(av[i]);
                    ffma2(acc[i][0], ap, b0.x);
                    ffma2(acc[i][1], ap, b0.y);
                    ffma2(acc[i][2], ap, b1.x);
                    ffma2(acc[i][3], ap, b1.y);
                }
            } else {
                float4 a0 = *(const float4*)&As[kk][ty64 * 4];
                ulonglong2 b0 = *(const ulonglong2*)&Bs[kk][tx64 * 8];
                ulonglong2 b1 = *(const ulonglong2*)&Bs[kk][tx64 * 8 + 4];
                float av[4] = {a0.x, a0.y, a0.z, a0.w};
                #pragma unroll
                for (int i = 0; i < RPT; i++) {
                    unsigned long long ap = pack2(av[i]);
                    ffma2(acc[i][0], ap, b0.x);
                    ffma2(acc[i][1], ap, b0.y);
                    ffma2(acc[i][2], ap, b1.x);
                    ffma2(acc[i][3], ap, b1.y);
                }
            }
        }
        __syncthreads();
    }

    #pragma unroll
    for (int i = 0; i < RPT; i++) {
        int mm, nb;
        if (TN_ == 128) { mm = ty128 * 4 + (i & 3) + ((i >> 2) << 6); nb = tx128 * 4; }
        else            { mm = ty64 * 4 + i;                          nb = tx64 * 8;  }
        const long long base = (long long)(row0 + mm) * ldc + col0;
        #pragma unroll
        for (int j = 0; j < 4; j++) {
            float2 p = unpack2(acc[i][j]);
            int gn;
            if (TN_ == 128) gn = (j < 2) ? (nb + j * 2) : (64 + nb + (j - 2) * 2);
            else            gn = nb + j * 2;
            float v0 = alpha * p.x;
            float v1 = alpha * p.y;
            if (bias) { v0 += bias[col0 + gn]; v1 += bias[col0 + gn + 1]; }
            if (relu) { v0 = fmaxf(v0, 0.f); v1 = fmaxf(v1, 0.f); }
            *(float2*)&C[base + gn] = make_float2(v0, v1);
        }
    }
}

// ---------------------- mma.sync bf16 3-term-split GEMM --------------------
// R11-proven form (interleaved term order; do NOT grow live registers here).
#define MPAD 24      // smem row stride in bf16 (48 B)
#define TILEB 6144   // one 128 x 16 tile: 128*MPAD*2 bytes
#define TILEU4 384   // TILEB / 16

__device__ __forceinline__ void ldsm4(uint32_t* r, uint32_t a) {
    asm volatile("ldmatrix.sync.aligned.m8n8.x4.shared.b16 {%0,%1,%2,%3}, [%4];"
        : "=r"(r[0]), "=r"(r[1]), "=r"(r[2]), "=r"(r[3]) : "r"(a));
}
__device__ __forceinline__ void ldsm2(uint32_t* r, uint32_t a) {
    asm volatile("ldmatrix.sync.aligned.m8n8.x2.shared.b16 {%0,%1}, [%2];"
        : "=r"(r[0]), "=r"(r[1]) : "r"(a));
}
__device__ __forceinline__ void mma16816(float* c, const uint32_t* a, const uint32_t* b) {
    asm volatile("mma.sync.aligned.m16n8k16.row.col.f32.bf16.bf16.f32 "
        "{%0,%1,%2,%3},{%4,%5,%6,%7},{%8,%9},{%0,%1,%2,%3};"
        : "+f"(c[0]), "+f"(c[1]), "+f"(c[2]), "+f"(c[3])
        : "r"(a[0]), "r"(a[1]), "r"(a[2]), "r"(a[3]), "r"(b[0]), "r"(b[1]));
}

template<int MODE>
__global__ __launch_bounds__(256, 2) void gemm_mma_t(
    const __nv_bfloat16* __restrict__ A0, const __nv_bfloat16* __restrict__ A1,
    const __nv_bfloat16* __restrict__ B0, const __nv_bfloat16* __restrict__ B1,
    const float* __restrict__ bias,
    float* __restrict__ Cf,
    __nv_bfloat16* __restrict__ Chi, __nv_bfloat16* __restrict__ Clo,
    int K, int N)      // MODE 0: fp32 C + bias; MODE 1: bias + relu + split bf16
{
    constexpr int NBUF = 4;
    extern __shared__ char dyns[];

    const int tid  = threadIdx.x;
    const int lane = tid & 31;
    const int wid  = tid >> 5;
    const int warp_m = wid >> 2;
    const int warp_n = wid & 3;
    const int row0 = blockIdx.y * 128;
    const int col0 = blockIdx.x * 128;
    const int ldu  = K >> 3;

    const int lrow = tid >> 1;
    const int lcol = tid & 1;
    const size_t aidx = (size_t)(row0 + lrow) * ldu + lcol;
    const size_t bidx = (size_t)(col0 + lrow) * ldu + lcol;
    const int sidx = lrow * 3 + lcol;

    const uint32_t su = (uint32_t)__cvta_generic_to_shared(dyns);

    float acc[4][4][4];
    #pragma unroll
    for (int m = 0; m < 4; m++)
        #pragma unroll
        for (int n = 0; n < 4; n++)
            #pragma unroll
            for (int j = 0; j < 4; j++) acc[m][n][j] = 0.f;

    const uint32_t a_off = ((uint32_t)(warp_m * 64 + (lane & 15)) * MPAD +
                            (uint32_t)(lane >> 4) * 8) * 2;
    const uint32_t b_off = ((uint32_t)(warp_n * 32 + (lane & 7)) * MPAD +
                            (uint32_t)((lane >> 3) & 1) * 8) * 2;

    uint4 sA0, sA1, sB0, sB1;
    sA0 = ((const uint4*)A0)[aidx];
    sA1 = ((const uint4*)A1)[aidx];
    sB0 = ((const uint4*)B0)[bidx];
    sB1 = ((const uint4*)B1)[bidx];
    {
        uint4* t = (uint4*)dyns;
        t[0 * TILEU4 + sidx] = sA0;
        t[1 * TILEU4 + sidx] = sA1;
        t[2 * TILEU4 + sidx] = sB0;
        t[3 * TILEU4 + sidx] = sB1;
    }
    __syncthreads();

    const int NC = K >> 4;
    for (int c = 0; c < NC; c++) {
        const int cur = c & 1;
        if (c + 1 < NC) {
            const size_t a2i = aidx + (size_t)(c + 1) * 2;
            const size_t b2i = bidx + (size_t)(c + 1) * 2;
            sA0 = ((const uint4*)A0)[a2i];
            sA1 = ((const uint4*)A1)[a2i];
            sB0 = ((const uint4*)B0)[b2i];
            sB1 = ((const uint4*)B1)[b2i];
        }

        const uint32_t tb = su + (uint32_t)(cur * NBUF) * TILEB;
        uint32_t bf0[4][2], bf1[4][2];
        #pragma unroll
        for (int nt = 0; nt < 4; nt++) {
            const uint32_t o = b_off + (uint32_t)(nt * 8 * MPAD * 2);
            ldsm2(bf0[nt], tb + 2 * TILEB + o);
            ldsm2(bf1[nt], tb + 3 * TILEB + o);
        }
        #pragma unroll
        for (int mt = 0; mt < 4; mt++) {
            const uint32_t o = a_off + (uint32_t)(mt * 16 * MPAD * 2);
            uint32_t a0r[4], a1r[4];
            ldsm4(a0r, tb + o);
            ldsm4(a1r, tb + TILEB + o);
            #pragma unroll
            for (int nt = 0; nt < 4; nt++) {
                mma16816(acc[mt][nt], a0r, bf0[nt]);
                mma16816(acc[mt][nt], a0r, bf1[nt]);
                mma16816(acc[mt][nt], a1r, bf0[nt]);
            }
        }

        if (c + 1 < NC) {
            uint4* t = (uint4*)(dyns + (size_t)((cur ^ 1) * NBUF) * TILEB);
            t[0 * TILEU4 + sidx] = sA0;
            t[1 * TILEU4 + sidx] = sA1;
            t[2 * TILEU4 + sidx] = sB0;
            t[3 * TILEU4 + sidx] = sB1;
        }
        __syncthreads();
    }

    // ---- epilogue
    #pragma unroll
    for (int mt = 0; mt < 4; mt++) {
        #pragma unroll
        for (int nt = 0; nt < 4; nt++) {
            const int r0 = row0 + warp_m * 64 + mt * 16 + (lane >> 2);
            const int cb = col0 + warp_n * 32 + nt * 8 + (lane & 3) * 2;
            const float* cc = acc[mt][nt];
            #pragma unroll
            for (int half = 0; half < 2; half++) {
                const int r = r0 + half * 8;
                float v0 = cc[half * 2 + 0] + bias[cb];
                float v1 = cc[half * 2 + 1] + bias[cb + 1];
                if (MODE == 0) {
                    *(float2*)&Cf[(size_t)r * N + cb] = make_float2(v0, v1);
                } else {
                    v0 = fmaxf(v0, 0.f); v1 = fmaxf(v1, 0.f);
                    __nv_bfloat16 h0 = __float2bfloat16(v0);
                    __nv_bfloat16 h1 = __float2bfloat16(v1);
                    __nv_bfloat162 hv; hv.x = h0; hv.y = h1;
                    __nv_bfloat162 lv;
                    lv.x = __float2bfloat16(v0 - __bfloat162float(h0));
                    lv.y = __float2bfloat16(v1 - __bfloat162float(h1));
                    *(__nv_bfloat162*)&Chi[(size_t)r * N + cb] = hv;
                    *(__nv_bfloat162*)&Clo[(size_t)r * N + cb] = lv;
                }
            }
        }
    }
}

// ------------------- logits on HMMA: 6-term 3-way-bf16 ---------------------
// logits[b,h] = (Qr @ Kr^T)/8 with Qr,Kr each 3-way bf16 split (q0+q1+q2).
// Terms {00,01,10,11,20,02} -> residual ~2^-23 (fp32-class for this chain).
// K=64 (4 chunks of 16); single-buffered static smem (6 tiles = 36 KB).
__global__ __launch_bounds__(256, 2) void gemm_logits(
    const __nv_bfloat16* __restrict__ Q0, const __nv_bfloat16* __restrict__ Q1,
    const __nv_bfloat16* __restrict__ Q2,
    const __nv_bfloat16* __restrict__ K0c, const __nv_bfloat16* __restrict__ K1c,
    const __nv_bfloat16* __restrict__ K2c,
    float* __restrict__ lg)
{
    __shared__ __align__(16) __nv_bfloat16 sm[6 * 128 * MPAD];

    const int tid  = threadIdx.x;
    const int lane = tid & 31;
    const int wid  = tid >> 5;
    const int warp_m = wid >> 2;
    const int warp_n = wid & 3;
    const int zb = blockIdx.z >> 4;
    const int zh = blockIdx.z & 15;
    const int row0 = blockIdx.y * 128;
    const int col0 = blockIdx.x * 128;

    const int lrow = tid >> 1;
    const int lcol = tid & 1;
    const size_t abase = (size_t)(zb * SS + row0 + lrow) * (DD / 8) + zh * 8 + lcol;
    const size_t bbase = (size_t)(zb * SS + col0 + lrow) * (DD / 8) + zh * 8 + lcol;
    const int sidx = lrow * 3 + lcol;

    const uint32_t su = (uint32_t)__cvta_generic_to_shared(sm);

    float acc[4][4][4];
    #pragma unroll
    for (int m = 0; m < 4; m++)
        #pragma unroll
        for (int n = 0; n < 4; n++)
            #pragma unroll
            for (int j = 0; j < 4; j++) acc[m][n][j] = 0.f;

    const uint32_t a_off = ((uint32_t)(warp_m * 64 + (lane & 15)) * MPAD +
                            (uint32_t)(lane >> 4) * 8) * 2;
    const uint32_t b_off = ((uint32_t)(warp_n * 32 + (lane & 7)) * MPAD +
                            (uint32_t)((lane >> 3) & 1) * 8) * 2;

    uint4* t = (uint4*)sm;
    #pragma unroll
    for (int c = 0; c < 4; c++) {
        t[0 * TILEU4 + sidx] = ((const uint4*)Q0)[abase + c * 2];
        t[1 * TILEU4 + sidx] = ((const uint4*)Q1)[abase + c * 2];
        t[2 * TILEU4 + sidx] = ((const uint4*)Q2)[abase + c * 2];
        t[3 * TILEU4 + sidx] = ((const uint4*)K0c)[bbase + c * 2];
        t[4 * TILEU4 + sidx] = ((const uint4*)K1c)[bbase + c * 2];
        t[5 * TILEU4 + sidx] = ((const uint4*)K2c)[bbase + c * 2];
        __syncthreads();

        uint32_t bf0[4][2], bf1[4][2], bf2[4][2];
        #pragma unroll
        for (int nt = 0; nt < 4; nt++) {
            const uint32_t o = b_off + (uint32_t)(nt * 8 * MPAD * 2);
            ldsm2(bf0[nt], su + 3 * TILEB + o);
            ldsm2(bf1[nt], su + 4 * TILEB + o);
            ldsm2(bf2[nt], su + 5 * TILEB + o);
        }
        #pragma unroll
        for (int mt = 0; mt < 4; mt++) {
            const uint32_t o = a_off + (uint32_t)(mt * 16 * MPAD * 2);
            uint32_t a0r[4], a1r[4], a2r[4];
            ldsm4(a0r, su + o);
            ldsm4(a1r, su + 1 * TILEB + o);
            ldsm4(a2r, su + 2 * TILEB + o);
            #pragma unroll
            for (int nt = 0; nt < 4; nt++) {
                mma16816(acc[mt][nt], a0r, bf0[nt]);
                mma16816(acc[mt][nt], a0r, bf1[nt]);
                mma16816(acc[mt][nt], a1r, bf0[nt]);
                mma16816(acc[mt][nt], a1r, bf1[nt]);
                mma16816(acc[mt][nt], a2r, bf0[nt]);
                mma16816(acc[mt][nt], a0r, bf2[nt]);
            }
        }
        __syncthreads();
    }

    // ---- epilogue: *0.125, write into the (b,h) logits block
    float* outp = lg + (size_t)zb * HH * SS * SS + (size_t)zh * SS * SS;
    #pragma unroll
    for (int mt = 0; mt < 4; mt++) {
        #pragma unroll
        for (int nt = 0; nt < 4; nt++) {
            const int r0 = row0 + warp_m * 64 + mt * 16 + (lane >> 2);
            const int cb = col0 + warp_n * 32 + nt * 8 + (lane & 3) * 2;
            const float* cc = acc[mt][nt];
            #pragma unroll
            for (int half = 0; half < 2; half++) {
                const int r = r0 + half * 8;
                *(float2*)&outp[(size_t)r * SS + cb] =
                    make_float2(0.125f * cc[half * 2 + 0],
                                0.125f * cc[half * 2 + 1]);
            }
        }
    }
}

// ------------------- weight transpose + bf16 hi/lo split -------------------
__global__ void tsplit_kernel(const float* __restrict__ in,
                              __nv_bfloat16* __restrict__ hiT,
                              __nv_bfloat16* __restrict__ loT,
                              int K, int N)
{
    __shared__ float t[32][33];
    const int n0 = blockIdx.x * 32;
    const int k0 = blockIdx.y * 32;
    const int tx = threadIdx.x, ty = threadIdx.y;   // 32 x 8
    #pragma unroll
    for (int i = 0; i < 32; i += 8)
        t[ty + i][tx] = in[(size_t)(k0 + ty + i) * N + n0 + tx];
    __syncthreads();
    #pragma unroll
    for (int i = 0; i < 32; i += 8) {
        float v = t[tx][ty + i];
        __nv_bfloat16 h = __float2bfloat16(v);
        size_t o = (size_t)(n0 + ty + i) * K + k0 + tx;
        hiT[o] = h;
        loT[o] = __float2bfloat16(v - __bfloat162float(h));
    }
}

// ------------------ elementwise 2-way fp32->bf16 split ---------------------
__global__ __launch_bounds__(256) void split2_kernel(
    const float* __restrict__ in,
    __nv_bfloat16* __restrict__ o0, __nv_bfloat16* __restrict__ o1)
{
    const int i0 = (blockIdx.x * 256 + threadIdx.x) * 4;
    float4 v = *(const float4*)(in + i0);
    const float* vv = &v.x;
    __nv_bfloat162 h2[2], l2[2];
    #pragma unroll
    for (int j = 0; j < 4; j++) {
        float x = vv[j];
        __nv_bfloat16 h = __float2bfloat16(x);
        ((__nv_bfloat16*)h2)[j] = h;
        ((__nv_bfloat16*)l2)[j] = __float2bfloat16(x - __bfloat162float(h));
    }
    *(uint2*)(o0 + i0) = *(uint2*)h2;
    *(uint2*)(o1 + i0) = *(uint2*)l2;
}

// ------------------ RoPE -> 3-way bf16 splits of q_rot, k_rot --------------
__global__ void rope_split_kernel(
    const float* __restrict__ q, const float* __restrict__ k,
    __nv_bfloat16* __restrict__ q0, __nv_bfloat16* __restrict__ q1,
    __nv_bfloat16* __restrict__ q2,
    __nv_bfloat16* __restrict__ k0, __nv_bfloat16* __restrict__ k1,
    __nv_bfloat16* __restrict__ k2)
{
    int warp = blockIdx.x * 8 + (threadIdx.x >> 5);
    int lane = threadIdx.x & 31;
    const int NROWS = BB * SS * HH;
    if (warp >= 2 * NROWS) return;
    const float* p;
    __nv_bfloat16 *o0, *o1, *o2;
    int r = warp;
    if (r < NROWS) { p = q + (long long)r * DH; o0 = q0; o1 = q1; o2 = q2; }
    else { r -= NROWS; p = k + (long long)r * DH; o0 = k0; o1 = k1; o2 = k2; }
    int s = (r / HH) & (SS - 1);

    float t0 = p[2 * lane];
    float t1 = p[2 * lane + 1];
    int m0 = (2 * lane) & 31;
    int m1 = (2 * lane + 1) & 31;
    const float c = 0.41524101186092026f;     // log2(10000)/32
    float fs = (float)s;
    float a  = fs * exp2f(-(float)m0 * c);
    float b  = fs * exp2f(-(float)m1 * c);
    float va = t0 * a - t1 * b;               // -> index lane
    float vb = t0 * b + t1 * a;               // -> index 32+lane

    long long base = (long long)(warp < 0 ? 0 : 0);  // silence unused
    (void)base;
    long long idx = (long long)r * DH;
    {
        __nv_bfloat16 h = __float2bfloat16(va);
        float rr = va - __bfloat162float(h);
        __nv_bfloat16 m = __float2bfloat16(rr);
        o0[idx + lane] = h;
        o1[idx + lane] = m;
        o2[idx + lane] = __float2bfloat16(rr - __bfloat162float(m));
    }
    {
        __nv_bfloat16 h = __float2bfloat16(vb);
        float rr = vb - __bfloat162float(h);
        __nv_bfloat16 m = __float2bfloat16(rr);
        o0[idx + 32 + lane] = h;
        o1[idx + 32 + lane] = m;
        o2[idx + 32 + lane] = __float2bfloat16(rr - __bfloat162float(m));
    }
}

// ------------------------------ softmax ------------------------------------
__global__ __launch_bounds__(256) void softmax_kernel(float* __restrict__ logits)
{
    long long row = blockIdx.x;
    float* p = logits + row * 2048;
    int tid = threadIdx.x;
    __shared__ float red[256];

    float v[8];
    float mx = -3.402823466e38f;
    #pragma unroll
    for (int i = 0; i < 8; i++) { v[i] = p[tid + i * 256]; mx = fmaxf(mx, v[i]); }
    red[tid] = mx; __syncthreads();
    for (int st = 128; st > 0; st >>= 1) {
        if (tid < st) red[tid] = fmaxf(red[tid], red[tid + st]);
        __syncthreads();
    }
    mx = red[0]; __syncthreads();

    float s = 0.f;
    #pragma unroll
    for (int i = 0; i < 8; i++) { v[i] = expf(v[i] - mx); s += v[i]; }
    red[tid] = s; __syncthreads();
    for (int st = 128; st > 0; st >>= 1) {
        if (tid < st) red[tid] += red[tid + st];
        __syncthreads();
    }
    float inv = 1.f / red[0];
    #pragma unroll
    for (int i = 0; i < 8; i++) p[tid + i * 256] = v[i] * inv;
}

// --------------------------- residual + layernorm --------------------------
__global__ __launch_bounds__(256) void add_ln_kernel(
    const float* __restrict__ a, const float* __restrict__ b,
    const float* __restrict__ g, const float* __restrict__ be,
    float* __restrict__ out,
    __nv_bfloat16* __restrict__ ohi, __nv_bfloat16* __restrict__ olo)
{
    __shared__ float red[256];
    long long row = blockIdx.x;
    int tid = threadIdx.x;
    const float* pa = a + row * DD;
    const float* pb = b + row * DD;

    float v[4]; float s = 0.f;
    #pragma unroll
    for (int i = 0; i < 4; i++) { int c = tid + i * 256; v[i] = pa[c] + pb[c]; s += v[i]; }
    red[tid] = s; __syncthreads();
    for (int st = 128; st > 0; st >>= 1) { if (tid < st) red[tid] += red[tid + st]; __syncthreads(); }
    float mean = red[0] * (1.f / 1024.f);
    __syncthreads();

    float s2 = 0.f;
    #pragma unroll
    for (int i = 0; i < 4; i++) { float d = v[i] - mean; s2 += d * d; }
    red[tid] = s2; __syncthreads();
    for (int st = 128; st > 0; st >>= 1) { if (tid < st) red[tid] += red[tid + st]; __syncthreads(); }
    float var = red[0] * (1.f / 1024.f);
    float rs = 1.f / sqrtf(var + 1e-5f);

    float* po = out + row * DD;
    #pragma unroll
    for (int i = 0; i < 4; i++) {
        int c = tid + i * 256;
        float val = (v[i] - mean) * rs * g[c] + be[c];
        po[c] = val;
        if (ohi) {
            __nv_bfloat16 h = __float2bfloat16(val);
            ohi[row * DD + c] = h;
            olo[row * DD + c] = __float2bfloat16(val - __bfloat162float(h));
        }
    }
}

// ------------------------------- launcher ----------------------------------
extern "C" void kernel_launch(void* const* d_in, const int* in_sizes, int n_in,
                              void* d_out, int out_size)
{
    (void)in_sizes; (void)n_in; (void)out_size;
    const float* x   = (const float*)d_in[0];
    const float* wq  = (const float*)d_in[1];
    const float* bq  = (const float*)d_in[2];
    const float* wk  = (const float*)d_in[3];
    const float* bk  = (const float*)d_in[4];
    const float* wv  = (const float*)d_in[5];
    const float* bv  = (const float*)d_in[6];
    const float* wo  = (const float*)d_in[7];
    const float* bo  = (const float*)d_in[8];
    const float* w1  = (const float*)d_in[9];
    const float* b1  = (const float*)d_in[10];
    const float* w2  = (const float*)d_in[11];
    const float* b2  = (const float*)d_in[12];
    const float* g1  = (const float*)d_in[13];
    const float* be1 = (const float*)d_in[14];
    const float* g2  = (const float*)d_in[15];
    const float* be2 = (const float*)d_in[16];
    float* out = (float*)d_out;

    float *q, *k, *v, *ctx, *att, *h, *ff2, *lg;
    __nv_bfloat16 *x0, *x1, *c0, *c1, *hhi, *hlo;
    __nv_bfloat16 *q0, *q1, *q2, *k0, *k1, *k2;
    __nv_bfloat16 *wvh, *wvl, *woh, *wol;
    __nv_bfloat16 *w1h, *w1l, *w2h, *w2l, *f1h, *f1l;
    cudaGetSymbolAddress((void**)&q,    g_q);
    cudaGetSymbolAddress((void**)&k,    g_k);
    cudaGetSymbolAddress((void**)&v,    g_v);
    cudaGetSymbolAddress((void**)&ctx,  g_ctx);
    cudaGetSymbolAddress((void**)&att,  g_att);
    cudaGetSymbolAddress((void**)&h,    g_h);
    cudaGetSymbolAddress((void**)&ff2,  g_ff2);
    cudaGetSymbolAddress((void**)&lg,   g_logits);
    cudaGetSymbolAddress((void**)&x0,   g_x0);
    cudaGetSymbolAddress((void**)&x1,   g_x1);
    cudaGetSymbolAddress((void**)&c0,   g_c0);
    cudaGetSymbolAddress((void**)&c1,   g_c1);
    cudaGetSymbolAddress((void**)&hhi,  g_h_hi);
    cudaGetSymbolAddress((void**)&hlo,  g_h_lo);
    cudaGetSymbolAddress((void**)&q0,   g_q0);
    cudaGetSymbolAddress((void**)&q1,   g_q1);
    cudaGetSymbolAddress((void**)&q2,   g_q2);
    cudaGetSymbolAddress((void**)&k0,   g_k0);
    cudaGetSymbolAddress((void**)&k1,   g_k1);
    cudaGetSymbolAddress((void**)&k2,   g_k2);
    cudaGetSymbolAddress((void**)&wvh,  g_wvt_hi); cudaGetSymbolAddress((void**)&wvl, g_wvt_lo);
    cudaGetSymbolAddress((void**)&woh,  g_wot_hi); cudaGetSymbolAddress((void**)&wol, g_wot_lo);
    cudaGetSymbolAddress((void**)&w1h,  g_w1t_hi); cudaGetSymbolAddress((void**)&w1l, g_w1t_lo);
    cudaGetSymbolAddress((void**)&w2h,  g_w2t_hi); cudaGetSymbolAddress((void**)&w2l, g_w2t_lo);
    cudaGetSymbolAddress((void**)&f1h,  g_ff1_hi); cudaGetSymbolAddress((void**)&f1l, g_ff1_lo);

    const int SM3 = 2 * 4 * TILEB;   // 49152 (double-buffered, 4 tiles/stage)
    cudaFuncSetAttribute(gemm_mma_t<0>, cudaFuncAttributeMaxDynamicSharedMemorySize, SM3);
    cudaFuncSetAttribute(gemm_mma_t<1>, cudaFuncAttributeMaxDynamicSharedMemorySize, SM3);

    dim3 blk(256);
    const long long sQ  = (long long)SS * DD;
    const long long sLb = (long long)HH * SS * SS;
    const long long sLh = (long long)SS * SS;

    dim3 gP(DD / 128, MM / TM, 1);

    // prep: x split (for V proj) + weight transpose/splits for mma path
    split2_kernel<<<MM * DD / 1024, 256>>>(x, x0, x1);
    tsplit_kernel<<<dim3(DD / 32, DD / 32), dim3(32, 8)>>>(wv, wvh, wvl, DD, DD);
    tsplit_kernel<<<dim3(DD / 32, DD / 32), dim3(32, 8)>>>(wo, woh, wol, DD, DD);
    tsplit_kernel<<<dim3(FF / 32, DD / 32), dim3(32, 8)>>>(w1, w1h, w1l, DD, FF);
    tsplit_kernel<<<dim3(DD / 32, FF / 32), dim3(32, 8)>>>(w2, w2h, w2l, FF, DD);

    // Q/K projections: fp32 (RoPE amplifies q/k error ~1e6x into the logits)
    gemm_t<128,0><<<gP, blk>>>(x, DD, 0, 0, wq, DD, 0, 0, q, DD, 0, 0, bq, DD, 1.f, 0);
    gemm_t<128,0><<<gP, blk>>>(x, DD, 0, 0, wk, DD, 0, 0, k, DD, 0, 0, bk, DD, 1.f, 0);

    // V projection: 3-term mma (linear path, err ~2^-17 OK)
    gemm_mma_t<0><<<dim3(DD/128, MM/128), blk, SM3>>>(
        x0, x1, wvh, wvl, bv, v, nullptr, nullptr, DD, DD);

    // RoPE -> 3-way bf16 splits of q_rot / k_rot
    rope_split_kernel<<<(2 * BB * SS * HH) / 8, 256>>>(q, k, q0, q1, q2, k0, k1, k2);

    // logits = (Qr @ Kr^T)/8 on HMMA via 6-term split (fp32-class residual)
    gemm_logits<<<dim3(SS / 128, SS / 128, BB * HH), blk>>>(
        q0, q1, q2, k0, k1, k2, lg);

    softmax_kernel<<<BB * HH * SS, 256>>>(lg);

    // ctx = attn @ V (fp32)
    gemm_t<64,0><<<dim3(1, SS / TM, BB * HH), blk>>>(
        lg, SS, sLb, sLh,  v, DD, sQ, DH,  ctx, DD, sQ, DH,
        nullptr, SS, 1.f, 0);

    // ctx split + output projection (3-term mma)
    split2_kernel<<<MM * DD / 1024, 256>>>(ctx, c0, c1);
    gemm_mma_t<0><<<dim3(DD/128, MM/128), blk, SM3>>>(
        c0, c1, woh, wol, bo, att, nullptr, nullptr, DD, DD);

    // h = LN(x + att), also emit bf16 split of h
    add_ln_kernel<<<MM, 256>>>(x, att, g1, be1, h, hhi, hlo);

    // FFN (3-term mma)
    gemm_mma_t<1><<<dim3(FF/128, MM/128), blk, SM3>>>(
        hhi, hlo, w1h, w1l, b1, nullptr, f1h, f1l, DD, FF);
    gemm_mma_t<0><<<dim3(DD/128, MM/128), blk, SM3>>>(
        f1h, f1l, w2h, w2l, b2, ff2, nullptr, nullptr, FF, DD);

    // out = LN(h + ff)
    add_ln_kernel<<<MM, 256>>>(h, ff2, g2, be2, out, nullptr, nullptr);
}